// round 1
// baseline (speedup 1.0000x reference)
#include <cuda_runtime.h>
#include <cuda_bf16.h>
#include <math.h>

// Problem constants
#define BATCH 32
#define SEQ   2048
#define HID   1024
#define KDIM  3072          // 3*HID
#define MROWS (BATCH*SEQ)   // 65536

// Scratch (device globals: allocation-free rule)
__device__ float g_w[BATCH * SEQ];            // softmax weights
__device__ float g_pp[8][BATCH * KDIM];       // pooled-trg partials (8 L-splits)

// ---------------------------------------------------------------------------
// Kernel 1: norm1[m] = || trg[m,:] @ W^T + bias ||  (fused GEMM -> row sumsq)
// 128x128 tile, BK=32, 256 threads, 8x8 per thread. Deterministic reduction.
// ---------------------------------------------------------------------------
#define BM 128
#define BN 128
#define BK 32
#define TM 8
#define TN 8

__global__ __launch_bounds__(256, 2)
void k_norm(const float* __restrict__ trg, const float* __restrict__ W,
            const float* __restrict__ bias, float* __restrict__ norm_out)
{
    __shared__ float As[BK][BM];
    __shared__ float Bs[BK][BN];
    __shared__ float rowsq[BM];
    __shared__ float redbuf[BM][17];   // padded, deterministic cross-tx reduce

    const int tid = threadIdx.x;
    const int tx = tid & 15;           // 0..15 -> N direction
    const int ty = tid >> 4;           // 0..15 -> M direction
    const int m0 = blockIdx.x * BM;

    if (tid < BM) rowsq[tid] = 0.0f;

    for (int n0 = 0; n0 < HID; n0 += BN) {
        float acc[TM][TN];
        #pragma unroll
        for (int i = 0; i < TM; ++i)
            #pragma unroll
            for (int j = 0; j < TN; ++j)
                acc[i][j] = 0.0f;

        for (int k0 = 0; k0 < KDIM; k0 += BK) {
            // Load A tile: 128 rows x 32 k (1024 float4 slots, 4 per thread)
            #pragma unroll
            for (int i = 0; i < 4; ++i) {
                int s  = tid + i * 256;
                int r  = s >> 3;            // row in tile
                int c4 = (s & 7) << 2;      // k offset (float4)
                float4 v = *(const float4*)(trg + (size_t)(m0 + r) * KDIM + k0 + c4);
                As[c4 + 0][r] = v.x; As[c4 + 1][r] = v.y;
                As[c4 + 2][r] = v.z; As[c4 + 3][r] = v.w;
            }
            // Load B tile: W[n0+r, k0+c]
            #pragma unroll
            for (int i = 0; i < 4; ++i) {
                int s  = tid + i * 256;
                int r  = s >> 3;
                int c4 = (s & 7) << 2;
                float4 v = *(const float4*)(W + (size_t)(n0 + r) * KDIM + k0 + c4);
                Bs[c4 + 0][r] = v.x; Bs[c4 + 1][r] = v.y;
                Bs[c4 + 2][r] = v.z; Bs[c4 + 3][r] = v.w;
            }
            __syncthreads();

            #pragma unroll
            for (int kk = 0; kk < BK; ++kk) {
                float a[TM], b[TN];
                #pragma unroll
                for (int i = 0; i < TM; ++i) a[i] = As[kk][ty * TM + i];
                #pragma unroll
                for (int j = 0; j < TN; ++j) b[j] = Bs[kk][tx * TN + j];
                #pragma unroll
                for (int i = 0; i < TM; ++i)
                    #pragma unroll
                    for (int j = 0; j < TN; ++j)
                        acc[i][j] = fmaf(a[i], b[j], acc[i][j]);
            }
            __syncthreads();
        }

        // Epilogue: +bias, square, deterministic per-row reduce
        float bv[TN];
        #pragma unroll
        for (int j = 0; j < TN; ++j) bv[j] = bias[n0 + tx * TN + j];

        #pragma unroll
        for (int i = 0; i < TM; ++i) {
            float p = 0.0f;
            #pragma unroll
            for (int j = 0; j < TN; ++j) {
                float v = acc[i][j] + bv[j];
                p = fmaf(v, v, p);
            }
            redbuf[ty * TM + i][tx] = p;
        }
        __syncthreads();
        if (tid < BM) {
            float s = rowsq[tid];
            #pragma unroll
            for (int j = 0; j < 16; ++j) s += redbuf[tid][j];
            rowsq[tid] = s;
        }
        __syncthreads();
    }

    if (tid < BM) norm_out[m0 + tid] = sqrtf(rowsq[tid]);
}

// ---------------------------------------------------------------------------
// Kernel 2: softmax over L per batch -> g_w
// ---------------------------------------------------------------------------
__global__ void k_softmax(const float* __restrict__ nrm)
{
    const int b = blockIdx.x;
    const int tid = threadIdx.x;
    __shared__ float red[256];
    const float* x = nrm + b * SEQ;

    float m = -1e30f;
    for (int l = tid; l < SEQ; l += 256) m = fmaxf(m, x[l]);
    red[tid] = m; __syncthreads();
    for (int s = 128; s > 0; s >>= 1) {
        if (tid < s) red[tid] = fmaxf(red[tid], red[tid + s]);
        __syncthreads();
    }
    float bm = red[0];
    __syncthreads();

    float sum = 0.0f;
    for (int l = tid; l < SEQ; l += 256) {
        float e = __expf(x[l] - bm);
        g_w[b * SEQ + l] = e;
        sum += e;
    }
    red[tid] = sum; __syncthreads();
    for (int s = 128; s > 0; s >>= 1) {
        if (tid < s) red[tid] += red[tid + s];
        __syncthreads();
    }
    float inv = 1.0f / red[0];
    for (int l = tid; l < SEQ; l += 256) g_w[b * SEQ + l] *= inv;
}

// ---------------------------------------------------------------------------
// Kernel 3: pooled partials: g_pp[ls][b,k] = sum_{l in split} w[b,l]*trg[b,l,k]
// grid (3 kchunks, 8 Lsplits, 32 batches), 256 threads, float4 per thread.
// No atomics -> deterministic.
// ---------------------------------------------------------------------------
__global__ void k_pool(const float* __restrict__ trg)
{
    const int kc = blockIdx.x;            // 0..2 (chunks of 1024 floats)
    const int ls = blockIdx.y;            // 0..7
    const int b  = blockIdx.z;            // 0..31
    const int tid = threadIdx.x;
    const int k0 = kc * 1024 + tid * 4;

    const float* base = trg + (size_t)b * SEQ * KDIM;
    float4 acc = make_float4(0.f, 0.f, 0.f, 0.f);

    const int l0 = ls * 256;
    #pragma unroll 4
    for (int l = l0; l < l0 + 256; ++l) {
        float wl = g_w[b * SEQ + l];
        float4 v = *(const float4*)(base + (size_t)l * KDIM + k0);
        acc.x = fmaf(wl, v.x, acc.x);
        acc.y = fmaf(wl, v.y, acc.y);
        acc.z = fmaf(wl, v.z, acc.z);
        acc.w = fmaf(wl, v.w, acc.w);
    }
    *(float4*)(&g_pp[ls][b * KDIM + k0]) = acc;
}

// ---------------------------------------------------------------------------
// Kernel 4: summ[b,h] = p[b,:] . W[h,:] + bias[h]
// grid (128, 32), 256 threads = 8 warps; one warp per h.
// ---------------------------------------------------------------------------
__global__ void k_out(const float* __restrict__ W, const float* __restrict__ bias,
                      float* __restrict__ summ)
{
    const int b = blockIdx.y;
    const int tid = threadIdx.x;
    const int lane = tid & 31;
    const int wid = tid >> 5;

    __shared__ float ps[KDIM];
    for (int k = tid; k < KDIM; k += 256) {
        float s = 0.0f;
        #pragma unroll
        for (int l = 0; l < 8; ++l) s += g_pp[l][b * KDIM + k];
        ps[k] = s;
    }
    __syncthreads();

    const int h = blockIdx.x * 8 + wid;
    const float* wr = W + (size_t)h * KDIM;
    float s = 0.0f;
    for (int k = lane * 4; k < KDIM; k += 128) {
        float4 v = *(const float4*)(wr + k);
        float4 u = *(const float4*)(ps + k);
        s = fmaf(v.x, u.x, s); s = fmaf(v.y, u.y, s);
        s = fmaf(v.z, u.z, s); s = fmaf(v.w, u.w, s);
    }
    #pragma unroll
    for (int o = 16; o > 0; o >>= 1) s += __shfl_xor_sync(0xffffffffu, s, o);
    if (lane == 0) summ[b * HID + h] = s + bias[h];
}

// ---------------------------------------------------------------------------
extern "C" void kernel_launch(void* const* d_in, const int* in_sizes, int n_in,
                              void* d_out, int out_size)
{
    const float* trg  = (const float*)d_in[0];
    // d_in[1] = src (unused, n_layers == 0)
    const float* W    = (const float*)d_in[2];
    const float* bias = (const float*)d_in[3];

    float* out   = (float*)d_out;
    float* summ  = out;                   // [32, 1024]
    float* norm1 = out + BATCH * HID;     // [32, 2048]

    k_norm<<<MROWS / BM, 256>>>(trg, W, bias, norm1);
    k_softmax<<<BATCH, 256>>>(norm1);
    k_pool<<<dim3(3, 8, BATCH), 256>>>(trg);
    k_out<<<dim3(HID / 8, BATCH), 256>>>(W, bias, summ);
}

// round 4
// speedup vs baseline: 3.3915x; 3.3915x over previous
#include <cuda_runtime.h>
#include <cuda_bf16.h>
#include <math.h>
#include <stdint.h>

// Problem constants
#define BATCH 32
#define SEQ   2048
#define HID   1024
#define KDIM  3072          // 3*HID
#define MROWS (BATCH*SEQ)   // 65536

// Scratch (device globals: allocation-free rule)
__device__ float g_w[BATCH * SEQ];            // softmax weights
__device__ float g_pp[8][BATCH * KDIM];       // pooled-trg partials (8 L-splits)

// ---------------------------------------------------------------------------
// helpers
// ---------------------------------------------------------------------------
__device__ __forceinline__ uint32_t smem_u32(const void* p) {
    uint32_t a;
    asm("{ .reg .u64 t; cvta.to.shared.u64 t, %1; cvt.u32.u64 %0, t; }"
        : "=r"(a) : "l"(p));
    return a;
}

__device__ __forceinline__ void cp16(uint32_t saddr, const void* gaddr) {
    asm volatile("cp.async.cg.shared.global [%0], [%1], 16;"
                 :: "r"(saddr), "l"(gaddr) : "memory");
}

__device__ __forceinline__ uint32_t to_tf32(float v) {
    uint32_t r;
    asm("cvt.rna.tf32.f32 %0, %1;" : "=r"(r) : "f"(v));
    return r;
}

__device__ __forceinline__ void mma_tf32(float& d0, float& d1, float& d2, float& d3,
                                         uint32_t a0, uint32_t a1, uint32_t a2, uint32_t a3,
                                         uint32_t b0, uint32_t b1) {
    asm volatile(
        "mma.sync.aligned.m16n8k8.row.col.f32.tf32.tf32.f32 "
        "{%0,%1,%2,%3}, {%4,%5,%6,%7}, {%8,%9}, {%0,%1,%2,%3};"
        : "+f"(d0), "+f"(d1), "+f"(d2), "+f"(d3)
        : "r"(a0), "r"(a1), "r"(a2), "r"(a3), "r"(b0), "r"(b1));
}

// ---------------------------------------------------------------------------
// Kernel 1: norm1[m] = || trg[m,:] @ W^T + bias ||
// tf32 mma.sync GEMM, 128x128 CTA tile, BK=32, double-buffered cp.async.
// 256 threads = 8 warps, warp grid 4(M) x 2(N), warp tile 32x64.
// Fused epilogue: +bias, square, deterministic row reduce, sqrt.
// ---------------------------------------------------------------------------
#define BK        32
#define RS        36                          // row stride (floats), conflict-free
#define TILE_F    (128 * RS)                  // floats per tile buffer
#define SMEM_NORM (4 * TILE_F * 4)            // A0,A1,B0,B1 -> 73728 B

__global__ __launch_bounds__(256, 2)
void k_norm_mma(const float* __restrict__ trg, const float* __restrict__ W,
                const float* __restrict__ bias, float* __restrict__ norm_out)
{
    extern __shared__ __align__(16) float smem[];
    float* As[2] = { smem,            smem + TILE_F };
    float* Bs[2] = { smem + 2*TILE_F, smem + 3*TILE_F };
    const uint32_t sA[2] = { smem_u32(As[0]), smem_u32(As[1]) };
    const uint32_t sB[2] = { smem_u32(Bs[0]), smem_u32(Bs[1]) };

    __shared__ float rowsq_s[128][2];

    const int tid  = threadIdx.x;
    const int lane = tid & 31;
    const int w    = tid >> 5;
    const int wy   = w >> 1;                  // 0..3  (M)
    const int wx   = w & 1;                   // 0..1  (N)
    const int g    = lane >> 2;               // groupID 0..7
    const int tig  = lane & 3;                // thread-in-group 0..3
    const int WM   = wy * 32;
    const int WN   = wx * 64;
    const size_t m0 = (size_t)blockIdx.x * 128;

    // load indexing: 1024 16B-chunks per tile, 4 per thread
    const int lrow[4] = { (tid + 0*256) >> 3, (tid + 1*256) >> 3,
                          (tid + 2*256) >> 3, (tid + 3*256) >> 3 };
    const int lcol4   = (tid & 7) * 4;        // same for all 4 chunks

    float rowsq[4] = {0.f, 0.f, 0.f, 0.f};

    for (int n0 = 0; n0 < HID; n0 += 128) {
        float acc[2][8][4];
        #pragma unroll
        for (int mt = 0; mt < 2; ++mt)
            #pragma unroll
            for (int nt = 0; nt < 8; ++nt)
                #pragma unroll
                for (int c = 0; c < 4; ++c) acc[mt][nt][c] = 0.f;

        // prologue: stage 0
        {
            #pragma unroll
            for (int i = 0; i < 4; ++i) {
                cp16(sA[0] + (lrow[i]*RS + lcol4)*4,
                     trg + (m0 + lrow[i]) * (size_t)KDIM + lcol4);
                cp16(sB[0] + (lrow[i]*RS + lcol4)*4,
                     W + (size_t)(n0 + lrow[i]) * KDIM + lcol4);
            }
            asm volatile("cp.async.commit_group;" ::: "memory");
        }

        for (int s = 0; s < KDIM / BK; ++s) {
            const int buf = s & 1;
            if (s + 1 < KDIM / BK) {
                const int nb = buf ^ 1;
                const int k1 = (s + 1) * BK;
                #pragma unroll
                for (int i = 0; i < 4; ++i) {
                    cp16(sA[nb] + (lrow[i]*RS + lcol4)*4,
                         trg + (m0 + lrow[i]) * (size_t)KDIM + k1 + lcol4);
                    cp16(sB[nb] + (lrow[i]*RS + lcol4)*4,
                         W + (size_t)(n0 + lrow[i]) * KDIM + k1 + lcol4);
                }
                asm volatile("cp.async.commit_group;" ::: "memory");
                asm volatile("cp.async.wait_group 1;" ::: "memory");
            } else {
                asm volatile("cp.async.wait_group 0;" ::: "memory");
            }
            __syncthreads();

            const float* A = As[buf];
            const float* B = Bs[buf];
            #pragma unroll
            for (int ks = 0; ks < BK / 8; ++ks) {
                const int ko = ks * 8;
                uint32_t af[2][4], bf[8][2];
                #pragma unroll
                for (int mt = 0; mt < 2; ++mt) {
                    const int r0 = (WM + mt*16 + g) * RS + ko + tig;
                    const int r1 = (WM + mt*16 + g + 8) * RS + ko + tig;
                    af[mt][0] = to_tf32(A[r0]);
                    af[mt][1] = to_tf32(A[r1]);
                    af[mt][2] = to_tf32(A[r0 + 4]);
                    af[mt][3] = to_tf32(A[r1 + 4]);
                }
                #pragma unroll
                for (int nt = 0; nt < 8; ++nt) {
                    const int rb = (WN + nt*8 + g) * RS + ko + tig;
                    bf[nt][0] = to_tf32(B[rb]);
                    bf[nt][1] = to_tf32(B[rb + 4]);
                }
                #pragma unroll
                for (int mt = 0; mt < 2; ++mt)
                    #pragma unroll
                    for (int nt = 0; nt < 8; ++nt)
                        mma_tf32(acc[mt][nt][0], acc[mt][nt][1],
                                 acc[mt][nt][2], acc[mt][nt][3],
                                 af[mt][0], af[mt][1], af[mt][2], af[mt][3],
                                 bf[nt][0], bf[nt][1]);
            }
            __syncthreads();
        }

        // epilogue: +bias, square-accumulate per row
        #pragma unroll
        for (int nt = 0; nt < 8; ++nt) {
            const int cb = n0 + WN + nt*8 + 2*tig;
            const float b0 = __ldg(bias + cb);
            const float b1 = __ldg(bias + cb + 1);
            #pragma unroll
            for (int mt = 0; mt < 2; ++mt) {
                float v0 = acc[mt][nt][0] + b0;
                float v1 = acc[mt][nt][1] + b1;
                float v2 = acc[mt][nt][2] + b0;
                float v3 = acc[mt][nt][3] + b1;
                rowsq[mt*2+0] = fmaf(v0, v0, rowsq[mt*2+0]);
                rowsq[mt*2+0] = fmaf(v1, v1, rowsq[mt*2+0]);
                rowsq[mt*2+1] = fmaf(v2, v2, rowsq[mt*2+1]);
                rowsq[mt*2+1] = fmaf(v3, v3, rowsq[mt*2+1]);
            }
        }
    }

    // quad reduce (lanes sharing same row): tig dimension
    #pragma unroll
    for (int i = 0; i < 4; ++i) {
        rowsq[i] += __shfl_xor_sync(0xffffffffu, rowsq[i], 1);
        rowsq[i] += __shfl_xor_sync(0xffffffffu, rowsq[i], 2);
    }
    if (tig == 0) {
        #pragma unroll
        for (int mt = 0; mt < 2; ++mt)
            #pragma unroll
            for (int i = 0; i < 2; ++i)
                rowsq_s[WM + mt*16 + i*8 + g][wx] = rowsq[mt*2 + i];
    }
    __syncthreads();
    if (tid < 128)
        norm_out[m0 + tid] = sqrtf(rowsq_s[tid][0] + rowsq_s[tid][1]);
}

// ---------------------------------------------------------------------------
// Kernel 2: softmax over L per batch -> g_w
// ---------------------------------------------------------------------------
__global__ void k_softmax(const float* __restrict__ nrm)
{
    const int b = blockIdx.x;
    const int tid = threadIdx.x;
    __shared__ float red[256];
    const float* x = nrm + b * SEQ;

    float m = -1e30f;
    for (int l = tid; l < SEQ; l += 256) m = fmaxf(m, x[l]);
    red[tid] = m; __syncthreads();
    for (int s = 128; s > 0; s >>= 1) {
        if (tid < s) red[tid] = fmaxf(red[tid], red[tid + s]);
        __syncthreads();
    }
    float bm = red[0];
    __syncthreads();

    float sum = 0.0f;
    for (int l = tid; l < SEQ; l += 256) {
        float e = __expf(x[l] - bm);
        g_w[b * SEQ + l] = e;
        sum += e;
    }
    red[tid] = sum; __syncthreads();
    for (int s = 128; s > 0; s >>= 1) {
        if (tid < s) red[tid] += red[tid + s];
        __syncthreads();
    }
    float inv = 1.0f / red[0];
    for (int l = tid; l < SEQ; l += 256) g_w[b * SEQ + l] *= inv;
}

// ---------------------------------------------------------------------------
// Kernel 3: pooled partials: g_pp[ls][b,k] = sum_{l in split} w[b,l]*trg[b,l,k]
// ---------------------------------------------------------------------------
__global__ void k_pool(const float* __restrict__ trg)
{
    const int kc = blockIdx.x;            // 0..2
    const int ls = blockIdx.y;            // 0..7
    const int b  = blockIdx.z;            // 0..31
    const int tid = threadIdx.x;
    const int k0 = kc * 1024 + tid * 4;

    const float* base = trg + (size_t)b * SEQ * KDIM;
    float4 acc = make_float4(0.f, 0.f, 0.f, 0.f);

    const int l0 = ls * 256;
    #pragma unroll 4
    for (int l = l0; l < l0 + 256; ++l) {
        float wl = g_w[b * SEQ + l];
        float4 v = *(const float4*)(base + (size_t)l * KDIM + k0);
        acc.x = fmaf(wl, v.x, acc.x);
        acc.y = fmaf(wl, v.y, acc.y);
        acc.z = fmaf(wl, v.z, acc.z);
        acc.w = fmaf(wl, v.w, acc.w);
    }
    *(float4*)(&g_pp[ls][b * KDIM + k0]) = acc;
}

// ---------------------------------------------------------------------------
// Kernel 4: summ[b,h] = p[b,:] . W[h,:] + bias[h]
// ---------------------------------------------------------------------------
__global__ void k_out(const float* __restrict__ W, const float* __restrict__ bias,
                      float* __restrict__ summ)
{
    const int b = blockIdx.y;
    const int tid = threadIdx.x;
    const int lane = tid & 31;
    const int wid = tid >> 5;

    __shared__ float ps[KDIM];
    for (int k = tid; k < KDIM; k += 256) {
        float s = 0.0f;
        #pragma unroll
        for (int l = 0; l < 8; ++l) s += g_pp[l][b * KDIM + k];
        ps[k] = s;
    }
    __syncthreads();

    const int h = blockIdx.x * 8 + wid;
    const float* wr = W + (size_t)h * KDIM;
    float s = 0.0f;
    for (int k = lane * 4; k < KDIM; k += 128) {
        float4 v = *(const float4*)(wr + k);
        float4 u = *(const float4*)(ps + k);
        s = fmaf(v.x, u.x, s); s = fmaf(v.y, u.y, s);
        s = fmaf(v.z, u.z, s); s = fmaf(v.w, u.w, s);
    }
    #pragma unroll
    for (int o = 16; o > 0; o >>= 1) s += __shfl_xor_sync(0xffffffffu, s, o);
    if (lane == 0) summ[b * HID + h] = s + bias[h];
}

// ---------------------------------------------------------------------------
extern "C" void kernel_launch(void* const* d_in, const int* in_sizes, int n_in,
                              void* d_out, int out_size)
{
    const float* trg  = (const float*)d_in[0];
    // d_in[1] = src (unused, n_layers == 0)
    const float* W    = (const float*)d_in[2];
    const float* bias = (const float*)d_in[3];

    float* out   = (float*)d_out;
    float* summ  = out;                   // [32, 1024]
    float* norm1 = out + BATCH * HID;     // [32, 2048]

    cudaFuncSetAttribute(k_norm_mma, cudaFuncAttributeMaxDynamicSharedMemorySize, SMEM_NORM);

    k_norm_mma<<<MROWS / 128, 256, SMEM_NORM>>>(trg, W, bias, norm1);
    k_softmax<<<BATCH, 256>>>(norm1);
    k_pool<<<dim3(3, 8, BATCH), 256>>>(trg);
    k_out<<<dim3(HID / 8, BATCH), 256>>>(W, bias, summ);
}

// round 5
// speedup vs baseline: 7.8892x; 2.3262x over previous
#include <cuda_runtime.h>
#include <cuda_fp16.h>
#include <cuda_bf16.h>
#include <math.h>
#include <stdint.h>

// Problem constants
#define BATCH 32
#define SEQ   2048
#define HID   1024
#define KDIM  3072          // 3*HID
#define MROWS (BATCH*SEQ)   // 65536

// Scratch (device globals: allocation-free rule)
__device__ float  g_w[BATCH * SEQ];            // softmax weights
__device__ float  g_pp[8][BATCH * KDIM];       // pooled-trg partials (8 L-splits)
__device__ float  g_np[8][MROWS];              // per-n-tile rowsq partials
__device__ __half g_trgh[(size_t)MROWS * KDIM];// fp16 trg (403 MB)
__device__ __half g_wh[(size_t)HID * KDIM];    // fp16 W   (6 MB)

// ---------------------------------------------------------------------------
// helpers
// ---------------------------------------------------------------------------
__device__ __forceinline__ uint32_t smem_u32(const void* p) {
    uint32_t a;
    asm("{ .reg .u64 t; cvta.to.shared.u64 t, %1; cvt.u32.u64 %0, t; }"
        : "=r"(a) : "l"(p));
    return a;
}

__device__ __forceinline__ void cp16(uint32_t saddr, const void* gaddr) {
    asm volatile("cp.async.cg.shared.global [%0], [%1], 16;"
                 :: "r"(saddr), "l"(gaddr) : "memory");
}

__device__ __forceinline__ void mma_f16(float& d0, float& d1, float& d2, float& d3,
                                        uint32_t a0, uint32_t a1, uint32_t a2, uint32_t a3,
                                        uint32_t b0, uint32_t b1) {
    asm volatile(
        "mma.sync.aligned.m16n8k16.row.col.f32.f16.f16.f32 "
        "{%0,%1,%2,%3}, {%4,%5,%6,%7}, {%8,%9}, {%0,%1,%2,%3};"
        : "+f"(d0), "+f"(d1), "+f"(d2), "+f"(d3)
        : "r"(a0), "r"(a1), "r"(a2), "r"(a3), "r"(b0), "r"(b1));
}

// ---------------------------------------------------------------------------
// Kernel 0: fp32 -> fp16 conversion, 8 elements/thread
// ---------------------------------------------------------------------------
__global__ __launch_bounds__(256)
void k_cvt8(const float* __restrict__ in, __half* __restrict__ out)
{
    const size_t i = ((size_t)blockIdx.x * 256 + threadIdx.x) * 8;
    float4 v0 = *(const float4*)(in + i);
    float4 v1 = *(const float4*)(in + i + 4);
    __half2 h0 = __floats2half2_rn(v0.x, v0.y);
    __half2 h1 = __floats2half2_rn(v0.z, v0.w);
    __half2 h2 = __floats2half2_rn(v1.x, v1.y);
    __half2 h3 = __floats2half2_rn(v1.z, v1.w);
    uint4 u;
    u.x = *(uint32_t*)&h0; u.y = *(uint32_t*)&h1;
    u.z = *(uint32_t*)&h2; u.w = *(uint32_t*)&h3;
    *(uint4*)(out + i) = u;
}

// ---------------------------------------------------------------------------
// Kernel 1: partial rowsq for one 128x128 output tile, full K.
// fp16 mma.sync m16n8k16, BK=64 halves, double-buffered cp.async.
// grid (8 n-tiles, 512 m-blocks) -> CTAs sharing m0 are adjacent (A L2 reuse).
// 256 threads = 8 warps, warp grid 4(M) x 2(N), warp tile 32x64.
// ---------------------------------------------------------------------------
#define BKH    64                              // k-halves per stage
#define RS_H   72                              // row stride in halves
#define TILE_H (128 * RS_H)                    // halves per tile buffer
#define SMEM_NORM (4 * TILE_H * 2)             // A0,A1,B0,B1 -> 73728 B
#define NSTG   (KDIM / BKH)                    // 48

__global__ __launch_bounds__(256, 2)
void k_norm_h(const float* __restrict__ bias)
{
    extern __shared__ __align__(16) __half smem[];
    __half* As[2] = { smem,            smem + TILE_H };
    __half* Bs[2] = { smem + 2*TILE_H, smem + 3*TILE_H };
    const uint32_t sA[2] = { smem_u32(As[0]), smem_u32(As[1]) };
    const uint32_t sB[2] = { smem_u32(Bs[0]), smem_u32(Bs[1]) };

    __shared__ float rowsq_s[128][2];

    const int tid  = threadIdx.x;
    const int lane = tid & 31;
    const int w    = tid >> 5;
    const int wy   = w >> 1;                  // 0..3  (M)
    const int wx   = w & 1;                   // 0..1  (N)
    const int g    = lane >> 2;               // 0..7
    const int tig  = lane & 3;                // 0..3
    const int WM   = wy * 32;
    const int WN   = wx * 64;
    const int    nx = blockIdx.x;             // n-tile 0..7
    const int    n0 = nx * 128;
    const size_t m0 = (size_t)blockIdx.y * 128;

    // load indexing: 1024 16B-chunks (8 halves) per tile, 4 per thread
    const int lrow[4] = { (tid + 0*256) >> 3, (tid + 1*256) >> 3,
                          (tid + 2*256) >> 3, (tid + 3*256) >> 3 };
    const int lcol8   = (tid & 7) * 8;        // half offset within row

    float acc[2][8][4];
    #pragma unroll
    for (int mt = 0; mt < 2; ++mt)
        #pragma unroll
        for (int nt = 0; nt < 8; ++nt)
            #pragma unroll
            for (int c = 0; c < 4; ++c) acc[mt][nt][c] = 0.f;

    // prologue
    #pragma unroll
    for (int i = 0; i < 4; ++i) {
        cp16(sA[0] + (lrow[i]*RS_H + lcol8)*2,
             g_trgh + (m0 + lrow[i]) * (size_t)KDIM + lcol8);
        cp16(sB[0] + (lrow[i]*RS_H + lcol8)*2,
             g_wh + (size_t)(n0 + lrow[i]) * KDIM + lcol8);
    }
    asm volatile("cp.async.commit_group;" ::: "memory");

    for (int s = 0; s < NSTG; ++s) {
        const int buf = s & 1;
        if (s + 1 < NSTG) {
            const int nb = buf ^ 1;
            const int k1 = (s + 1) * BKH;
            #pragma unroll
            for (int i = 0; i < 4; ++i) {
                cp16(sA[nb] + (lrow[i]*RS_H + lcol8)*2,
                     g_trgh + (m0 + lrow[i]) * (size_t)KDIM + k1 + lcol8);
                cp16(sB[nb] + (lrow[i]*RS_H + lcol8)*2,
                     g_wh + (size_t)(n0 + lrow[i]) * KDIM + k1 + lcol8);
            }
            asm volatile("cp.async.commit_group;" ::: "memory");
            asm volatile("cp.async.wait_group 1;" ::: "memory");
        } else {
            asm volatile("cp.async.wait_group 0;" ::: "memory");
        }
        __syncthreads();

        const __half* A = As[buf];
        const __half* B = Bs[buf];
        #pragma unroll
        for (int ks = 0; ks < BKH / 16; ++ks) {
            const int ko = ks * 16;
            uint32_t af[2][4], bf[8][2];
            #pragma unroll
            for (int mt = 0; mt < 2; ++mt) {
                const int r0 = (WM + mt*16 + g)     * RS_H + ko + 2*tig;
                const int r1 = (WM + mt*16 + g + 8) * RS_H + ko + 2*tig;
                af[mt][0] = *(const uint32_t*)(A + r0);
                af[mt][1] = *(const uint32_t*)(A + r1);
                af[mt][2] = *(const uint32_t*)(A + r0 + 8);
                af[mt][3] = *(const uint32_t*)(A + r1 + 8);
            }
            #pragma unroll
            for (int nt = 0; nt < 8; ++nt) {
                const int rb = (WN + nt*8 + g) * RS_H + ko + 2*tig;
                bf[nt][0] = *(const uint32_t*)(B + rb);
                bf[nt][1] = *(const uint32_t*)(B + rb + 8);
            }
            #pragma unroll
            for (int mt = 0; mt < 2; ++mt)
                #pragma unroll
                for (int nt = 0; nt < 8; ++nt)
                    mma_f16(acc[mt][nt][0], acc[mt][nt][1],
                            acc[mt][nt][2], acc[mt][nt][3],
                            af[mt][0], af[mt][1], af[mt][2], af[mt][3],
                            bf[nt][0], bf[nt][1]);
        }
        __syncthreads();
    }

    // epilogue: +bias, square-accumulate per row (partial over this n-tile)
    float rowsq[4] = {0.f, 0.f, 0.f, 0.f};
    #pragma unroll
    for (int nt = 0; nt < 8; ++nt) {
        const int cb = n0 + WN + nt*8 + 2*tig;
        const float b0 = __ldg(bias + cb);
        const float b1 = __ldg(bias + cb + 1);
        #pragma unroll
        for (int mt = 0; mt < 2; ++mt) {
            float v0 = acc[mt][nt][0] + b0;
            float v1 = acc[mt][nt][1] + b1;
            float v2 = acc[mt][nt][2] + b0;
            float v3 = acc[mt][nt][3] + b1;
            rowsq[mt*2+0] = fmaf(v0, v0, rowsq[mt*2+0]);
            rowsq[mt*2+0] = fmaf(v1, v1, rowsq[mt*2+0]);
            rowsq[mt*2+1] = fmaf(v2, v2, rowsq[mt*2+1]);
            rowsq[mt*2+1] = fmaf(v3, v3, rowsq[mt*2+1]);
        }
    }
    #pragma unroll
    for (int i = 0; i < 4; ++i) {
        rowsq[i] += __shfl_xor_sync(0xffffffffu, rowsq[i], 1);
        rowsq[i] += __shfl_xor_sync(0xffffffffu, rowsq[i], 2);
    }
    if (tig == 0) {
        #pragma unroll
        for (int mt = 0; mt < 2; ++mt)
            #pragma unroll
            for (int i = 0; i < 2; ++i)
                rowsq_s[WM + mt*16 + i*8 + g][wx] = rowsq[mt*2 + i];
    }
    __syncthreads();
    if (tid < 128)
        g_np[nx][m0 + tid] = rowsq_s[tid][0] + rowsq_s[tid][1];
}

// ---------------------------------------------------------------------------
// Kernel 2: combine rowsq partials -> norm1, then softmax over L -> g_w
// ---------------------------------------------------------------------------
__global__ void k_softmax(float* __restrict__ norm1)
{
    const int b = blockIdx.x;
    const int tid = threadIdx.x;
    __shared__ float red[256];

    for (int l = tid; l < SEQ; l += 256) {
        const int m = b * SEQ + l;
        float s = 0.f;
        #pragma unroll
        for (int j = 0; j < 8; ++j) s += g_np[j][m];
        norm1[m] = sqrtf(s);
    }
    __syncthreads();

    const float* x = norm1 + b * SEQ;
    float m = -1e30f;
    for (int l = tid; l < SEQ; l += 256) m = fmaxf(m, x[l]);
    red[tid] = m; __syncthreads();
    for (int s = 128; s > 0; s >>= 1) {
        if (tid < s) red[tid] = fmaxf(red[tid], red[tid + s]);
        __syncthreads();
    }
    float bm = red[0];
    __syncthreads();

    float sum = 0.0f;
    for (int l = tid; l < SEQ; l += 256) {
        float e = __expf(x[l] - bm);
        g_w[b * SEQ + l] = e;
        sum += e;
    }
    red[tid] = sum; __syncthreads();
    for (int s = 128; s > 0; s >>= 1) {
        if (tid < s) red[tid] += red[tid + s];
        __syncthreads();
    }
    float inv = 1.0f / red[0];
    for (int l = tid; l < SEQ; l += 256) g_w[b * SEQ + l] *= inv;
}

// ---------------------------------------------------------------------------
// Kernel 3: pooled partials from fp16 trg: g_pp[ls][b,k] = sum w[b,l]*trg[b,l,k]
// ---------------------------------------------------------------------------
__global__ void k_pool(void)
{
    const int kc = blockIdx.x;            // 0..2
    const int ls = blockIdx.y;            // 0..7
    const int b  = blockIdx.z;            // 0..31
    const int tid = threadIdx.x;
    const int k0 = kc * 1024 + tid * 4;

    const __half* base = g_trgh + (size_t)b * SEQ * KDIM;
    float4 acc = make_float4(0.f, 0.f, 0.f, 0.f);

    const int l0 = ls * 256;
    #pragma unroll 4
    for (int l = l0; l < l0 + 256; ++l) {
        float wl = g_w[b * SEQ + l];
        uint2 raw = *(const uint2*)(base + (size_t)l * KDIM + k0);
        float2 f0 = __half22float2(*(__half2*)&raw.x);
        float2 f1 = __half22float2(*(__half2*)&raw.y);
        acc.x = fmaf(wl, f0.x, acc.x);
        acc.y = fmaf(wl, f0.y, acc.y);
        acc.z = fmaf(wl, f1.x, acc.z);
        acc.w = fmaf(wl, f1.y, acc.w);
    }
    *(float4*)(&g_pp[ls][b * KDIM + k0]) = acc;
}

// ---------------------------------------------------------------------------
// Kernel 4: summ[b,h] = p[b,:] . W[h,:] + bias[h]   (fp32 W for accuracy)
// ---------------------------------------------------------------------------
__global__ void k_out(const float* __restrict__ W, const float* __restrict__ bias,
                      float* __restrict__ summ)
{
    const int b = blockIdx.y;
    const int tid = threadIdx.x;
    const int lane = tid & 31;
    const int wid = tid >> 5;

    __shared__ float ps[KDIM];
    for (int k = tid; k < KDIM; k += 256) {
        float s = 0.0f;
        #pragma unroll
        for (int l = 0; l < 8; ++l) s += g_pp[l][b * KDIM + k];
        ps[k] = s;
    }
    __syncthreads();

    const int h = blockIdx.x * 8 + wid;
    const float* wr = W + (size_t)h * KDIM;
    float s = 0.0f;
    for (int k = lane * 4; k < KDIM; k += 128) {
        float4 v = *(const float4*)(wr + k);
        float4 u = *(const float4*)(ps + k);
        s = fmaf(v.x, u.x, s); s = fmaf(v.y, u.y, s);
        s = fmaf(v.z, u.z, s); s = fmaf(v.w, u.w, s);
    }
    #pragma unroll
    for (int o = 16; o > 0; o >>= 1) s += __shfl_xor_sync(0xffffffffu, s, o);
    if (lane == 0) summ[b * HID + h] = s + bias[h];
}

// ---------------------------------------------------------------------------
extern "C" void kernel_launch(void* const* d_in, const int* in_sizes, int n_in,
                              void* d_out, int out_size)
{
    const float* trg  = (const float*)d_in[0];
    // d_in[1] = src (unused, n_layers == 0)
    const float* W    = (const float*)d_in[2];
    const float* bias = (const float*)d_in[3];

    float* out   = (float*)d_out;
    float* summ  = out;                   // [32, 1024]
    float* norm1 = out + BATCH * HID;     // [32, 2048]

    __half* trgh; cudaGetSymbolAddress((void**)&trgh, g_trgh);
    __half* wh;   cudaGetSymbolAddress((void**)&wh,   g_wh);

    cudaFuncSetAttribute(k_norm_h, cudaFuncAttributeMaxDynamicSharedMemorySize, SMEM_NORM);

    k_cvt8<<<(HID * KDIM) / (256 * 8), 256>>>(W, wh);
    k_cvt8<<<((size_t)MROWS * KDIM) / (256 * 8), 256>>>(trg, trgh);
    k_norm_h<<<dim3(8, MROWS / 128), 256, SMEM_NORM>>>(bias);
    k_softmax<<<BATCH, 256>>>(norm1);
    k_pool<<<dim3(3, 8, BATCH), 256>>>();
    k_out<<<dim3(HID / 8, BATCH), 256>>>(W, bias, summ);
}

// round 6
// speedup vs baseline: 9.6922x; 1.2285x over previous
#include <cuda_runtime.h>
#include <cuda_fp16.h>
#include <cuda_bf16.h>
#include <math.h>
#include <stdint.h>

// Problem constants
#define BATCH 32
#define SEQ   2048
#define HID   1024
#define KDIM  3072          // 3*HID
#define MROWS (BATCH*SEQ)   // 65536

// Scratch (device globals: allocation-free rule)
__device__ float  g_w[BATCH * SEQ];            // softmax weights
__device__ float  g_pp[8][BATCH * KDIM];       // pooled-trg partials (8 L-splits)
__device__ float  g_np[8][MROWS];              // per-n-tile rowsq partials
__device__ __half g_trgh[(size_t)MROWS * KDIM];// fp16 trg (403 MB)
__device__ __half g_wh[(size_t)HID * KDIM];    // fp16 W   (6 MB)

// ---------------------------------------------------------------------------
// helpers
// ---------------------------------------------------------------------------
__device__ __forceinline__ uint32_t smem_u32(const void* p) {
    uint32_t a;
    asm("{ .reg .u64 t; cvta.to.shared.u64 t, %1; cvt.u32.u64 %0, t; }"
        : "=r"(a) : "l"(p));
    return a;
}

__device__ __forceinline__ void cp16(uint32_t saddr, const void* gaddr) {
    asm volatile("cp.async.cg.shared.global [%0], [%1], 16;"
                 :: "r"(saddr), "l"(gaddr) : "memory");
}

__device__ __forceinline__ void ldsm_x4(uint32_t& r0, uint32_t& r1,
                                        uint32_t& r2, uint32_t& r3, uint32_t addr) {
    asm volatile("ldmatrix.sync.aligned.m8n8.x4.shared.b16 {%0,%1,%2,%3}, [%4];"
                 : "=r"(r0), "=r"(r1), "=r"(r2), "=r"(r3) : "r"(addr));
}

__device__ __forceinline__ void mma_f16(float& d0, float& d1, float& d2, float& d3,
                                        uint32_t a0, uint32_t a1, uint32_t a2, uint32_t a3,
                                        uint32_t b0, uint32_t b1) {
    asm volatile(
        "mma.sync.aligned.m16n8k16.row.col.f32.f16.f16.f32 "
        "{%0,%1,%2,%3}, {%4,%5,%6,%7}, {%8,%9}, {%0,%1,%2,%3};"
        : "+f"(d0), "+f"(d1), "+f"(d2), "+f"(d3)
        : "r"(a0), "r"(a1), "r"(a2), "r"(a3), "r"(b0), "r"(b1));
}

// ---------------------------------------------------------------------------
// Kernel 0: fp32 -> fp16 conversion, 8 elements/thread
// ---------------------------------------------------------------------------
__global__ __launch_bounds__(256)
void k_cvt8(const float* __restrict__ in, __half* __restrict__ out)
{
    const size_t i = ((size_t)blockIdx.x * 256 + threadIdx.x) * 8;
    float4 v0 = *(const float4*)(in + i);
    float4 v1 = *(const float4*)(in + i + 4);
    __half2 h0 = __floats2half2_rn(v0.x, v0.y);
    __half2 h1 = __floats2half2_rn(v0.z, v0.w);
    __half2 h2 = __floats2half2_rn(v1.x, v1.y);
    __half2 h3 = __floats2half2_rn(v1.z, v1.w);
    uint4 u;
    u.x = *(uint32_t*)&h0; u.y = *(uint32_t*)&h1;
    u.z = *(uint32_t*)&h2; u.w = *(uint32_t*)&h3;
    *(uint4*)(out + i) = u;
}

// ---------------------------------------------------------------------------
// Kernel 1: partial rowsq for one 128x128 output tile, full K.
// fp16 mma.sync m16n8k16 + ldmatrix.x4, BK=64 halves (=128B, full SW128 row),
// XOR-swizzled smem, double-buffered cp.async.
// grid (8 n-tiles, 512 m-blocks) -> CTAs sharing m0 adjacent (A L2 reuse).
// 256 threads = 8 warps, warp grid 4(M) x 2(N), warp tile 32x64.
// ---------------------------------------------------------------------------
#define BKH    64                              // k-halves per stage
#define TILE_B (128 * 128)                     // bytes per tile buffer (16 KB)
#define SMEM_NORM (4 * TILE_B)                 // A0,A1,B0,B1 -> 64 KB
#define NSTG   (KDIM / BKH)                    // 48

__global__ __launch_bounds__(256, 2)
void k_norm_h(const float* __restrict__ bias)
{
    extern __shared__ __align__(128) char smem[];
    const uint32_t sb = smem_u32(smem);
    const uint32_t sA[2] = { sb,            sb + TILE_B };
    const uint32_t sB[2] = { sb + 2*TILE_B, sb + 3*TILE_B };

    __shared__ float rowsq_s[128][2];

    const int tid  = threadIdx.x;
    const int lane = tid & 31;
    const int w    = tid >> 5;
    const int wy   = w >> 1;                  // 0..3  (M)
    const int wx   = w & 1;                   // 0..1  (N)
    const int g    = lane >> 2;               // 0..7
    const int tig  = lane & 3;                // 0..3
    const int WM   = wy * 32;
    const int WN   = wx * 64;
    const int    nx = blockIdx.x;             // n-tile 0..7
    const int    n0 = nx * 128;
    const size_t m0 = (size_t)blockIdx.y * 128;

    // ---- cp.async indexing: 1024 16B-chunks per tile, 4 per thread ----
    const int lrow[4] = { (tid + 0*256) >> 3, (tid + 1*256) >> 3,
                          (tid + 2*256) >> 3, (tid + 3*256) >> 3 };
    const int lc     = tid & 7;               // chunk index
    const int lcol8  = lc * 8;                // half offset in gmem row
    // swizzled store offsets (per chunk): row*128 + ((c ^ (row&7))*16)
    int soff[4];
    #pragma unroll
    for (int i = 0; i < 4; ++i)
        soff[i] = lrow[i] * 128 + ((lc ^ (lrow[i] & 7)) << 4);

    // ---- ldmatrix per-lane row bases ----
    const int sub  = ((lane >> 3) & 1) * 8 + (lane & 7);  // row-in-16 block
    const int hi   = (lane >> 4) & 1;                     // k-half selector
    const int mod7 = lane & 7;                            // swizzle row mod
    int aoff[2], boff[4];
    #pragma unroll
    for (int mt = 0; mt < 2; ++mt) aoff[mt] = (WM + mt*16 + sub) * 128;
    #pragma unroll
    for (int j = 0; j < 4; ++j)    boff[j]  = (WN + j*16  + sub) * 128;

    float acc[2][8][4];
    #pragma unroll
    for (int mt = 0; mt < 2; ++mt)
        #pragma unroll
        for (int nt = 0; nt < 8; ++nt)
            #pragma unroll
            for (int c = 0; c < 4; ++c) acc[mt][nt][c] = 0.f;

    // prologue: stage 0
    #pragma unroll
    for (int i = 0; i < 4; ++i) {
        cp16(sA[0] + soff[i], g_trgh + (m0 + lrow[i]) * (size_t)KDIM + lcol8);
        cp16(sB[0] + soff[i], g_wh + (size_t)(n0 + lrow[i]) * KDIM + lcol8);
    }
    asm volatile("cp.async.commit_group;" ::: "memory");

    for (int s = 0; s < NSTG; ++s) {
        const int buf = s & 1;
        if (s + 1 < NSTG) {
            const int nb = buf ^ 1;
            const int k1 = (s + 1) * BKH;
            #pragma unroll
            for (int i = 0; i < 4; ++i) {
                cp16(sA[nb] + soff[i],
                     g_trgh + (m0 + lrow[i]) * (size_t)KDIM + k1 + lcol8);
                cp16(sB[nb] + soff[i],
                     g_wh + (size_t)(n0 + lrow[i]) * KDIM + k1 + lcol8);
            }
            asm volatile("cp.async.commit_group;" ::: "memory");
            asm volatile("cp.async.wait_group 1;" ::: "memory");
        } else {
            asm volatile("cp.async.wait_group 0;" ::: "memory");
        }
        __syncthreads();

        const uint32_t bA = sA[buf];
        const uint32_t bB = sB[buf];
        #pragma unroll
        for (int ks = 0; ks < BKH / 16; ++ks) {
            // shared swizzled chunk offset for this k-step (all 6 LDSMs)
            const uint32_t sw = (uint32_t)(((ks*2 + hi) ^ mod7) << 4);
            uint32_t af[2][4], bf[8][2];
            #pragma unroll
            for (int mt = 0; mt < 2; ++mt)
                ldsm_x4(af[mt][0], af[mt][1], af[mt][2], af[mt][3],
                        bA + aoff[mt] + sw);
            #pragma unroll
            for (int j = 0; j < 4; ++j)
                ldsm_x4(bf[2*j][0], bf[2*j+1][0], bf[2*j][1], bf[2*j+1][1],
                        bB + boff[j] + sw);
            #pragma unroll
            for (int mt = 0; mt < 2; ++mt)
                #pragma unroll
                for (int nt = 0; nt < 8; ++nt)
                    mma_f16(acc[mt][nt][0], acc[mt][nt][1],
                            acc[mt][nt][2], acc[mt][nt][3],
                            af[mt][0], af[mt][1], af[mt][2], af[mt][3],
                            bf[nt][0], bf[nt][1]);
        }
        __syncthreads();
    }

    // epilogue: +bias, square-accumulate per row (partial over this n-tile)
    float rowsq[4] = {0.f, 0.f, 0.f, 0.f};
    #pragma unroll
    for (int nt = 0; nt < 8; ++nt) {
        const int cb = n0 + WN + nt*8 + 2*tig;
        const float b0 = __ldg(bias + cb);
        const float b1 = __ldg(bias + cb + 1);
        #pragma unroll
        for (int mt = 0; mt < 2; ++mt) {
            float v0 = acc[mt][nt][0] + b0;
            float v1 = acc[mt][nt][1] + b1;
            float v2 = acc[mt][nt][2] + b0;
            float v3 = acc[mt][nt][3] + b1;
            rowsq[mt*2+0] = fmaf(v0, v0, rowsq[mt*2+0]);
            rowsq[mt*2+0] = fmaf(v1, v1, rowsq[mt*2+0]);
            rowsq[mt*2+1] = fmaf(v2, v2, rowsq[mt*2+1]);
            rowsq[mt*2+1] = fmaf(v3, v3, rowsq[mt*2+1]);
        }
    }
    #pragma unroll
    for (int i = 0; i < 4; ++i) {
        rowsq[i] += __shfl_xor_sync(0xffffffffu, rowsq[i], 1);
        rowsq[i] += __shfl_xor_sync(0xffffffffu, rowsq[i], 2);
    }
    if (tig == 0) {
        #pragma unroll
        for (int mt = 0; mt < 2; ++mt)
            #pragma unroll
            for (int i = 0; i < 2; ++i)
                rowsq_s[WM + mt*16 + i*8 + g][wx] = rowsq[mt*2 + i];
    }
    __syncthreads();
    if (tid < 128)
        g_np[nx][m0 + tid] = rowsq_s[tid][0] + rowsq_s[tid][1];
}

// ---------------------------------------------------------------------------
// Kernel 2: combine rowsq partials -> norm1, then softmax over L -> g_w
// ---------------------------------------------------------------------------
__global__ void k_softmax(float* __restrict__ norm1)
{
    const int b = blockIdx.x;
    const int tid = threadIdx.x;
    __shared__ float red[256];

    for (int l = tid; l < SEQ; l += 256) {
        const int m = b * SEQ + l;
        float s = 0.f;
        #pragma unroll
        for (int j = 0; j < 8; ++j) s += g_np[j][m];
        norm1[m] = sqrtf(s);
    }
    __syncthreads();

    const float* x = norm1 + b * SEQ;
    float m = -1e30f;
    for (int l = tid; l < SEQ; l += 256) m = fmaxf(m, x[l]);
    red[tid] = m; __syncthreads();
    for (int s = 128; s > 0; s >>= 1) {
        if (tid < s) red[tid] = fmaxf(red[tid], red[tid + s]);
        __syncthreads();
    }
    float bm = red[0];
    __syncthreads();

    float sum = 0.0f;
    for (int l = tid; l < SEQ; l += 256) {
        float e = __expf(x[l] - bm);
        g_w[b * SEQ + l] = e;
        sum += e;
    }
    red[tid] = sum; __syncthreads();
    for (int s = 128; s > 0; s >>= 1) {
        if (tid < s) red[tid] += red[tid + s];
        __syncthreads();
    }
    float inv = 1.0f / red[0];
    for (int l = tid; l < SEQ; l += 256) g_w[b * SEQ + l] *= inv;
}

// ---------------------------------------------------------------------------
// Kernel 3: pooled partials from fp16 trg: g_pp[ls][b,k] = sum w[b,l]*trg[b,l,k]
// ---------------------------------------------------------------------------
__global__ void k_pool(void)
{
    const int kc = blockIdx.x;            // 0..2
    const int ls = blockIdx.y;            // 0..7
    const int b  = blockIdx.z;            // 0..31
    const int tid = threadIdx.x;
    const int k0 = kc * 1024 + tid * 4;

    const __half* base = g_trgh + (size_t)b * SEQ * KDIM;
    float4 acc = make_float4(0.f, 0.f, 0.f, 0.f);

    const int l0 = ls * 256;
    #pragma unroll 4
    for (int l = l0; l < l0 + 256; ++l) {
        float wl = g_w[b * SEQ + l];
        uint2 raw = *(const uint2*)(base + (size_t)l * KDIM + k0);
        float2 f0 = __half22float2(*(__half2*)&raw.x);
        float2 f1 = __half22float2(*(__half2*)&raw.y);
        acc.x = fmaf(wl, f0.x, acc.x);
        acc.y = fmaf(wl, f0.y, acc.y);
        acc.z = fmaf(wl, f1.x, acc.z);
        acc.w = fmaf(wl, f1.y, acc.w);
    }
    *(float4*)(&g_pp[ls][b * KDIM + k0]) = acc;
}

// ---------------------------------------------------------------------------
// Kernel 4: summ[b,h] = p[b,:] . W[h,:] + bias[h]   (fp32 W for accuracy)
// ---------------------------------------------------------------------------
__global__ void k_out(const float* __restrict__ W, const float* __restrict__ bias,
                      float* __restrict__ summ)
{
    const int b = blockIdx.y;
    const int tid = threadIdx.x;
    const int lane = tid & 31;
    const int wid = tid >> 5;

    __shared__ float ps[KDIM];
    for (int k = tid; k < KDIM; k += 256) {
        float s = 0.0f;
        #pragma unroll
        for (int l = 0; l < 8; ++l) s += g_pp[l][b * KDIM + k];
        ps[k] = s;
    }
    __syncthreads();

    const int h = blockIdx.x * 8 + wid;
    const float* wr = W + (size_t)h * KDIM;
    float s = 0.0f;
    for (int k = lane * 4; k < KDIM; k += 128) {
        float4 v = *(const float4*)(wr + k);
        float4 u = *(const float4*)(ps + k);
        s = fmaf(v.x, u.x, s); s = fmaf(v.y, u.y, s);
        s = fmaf(v.z, u.z, s); s = fmaf(v.w, u.w, s);
    }
    #pragma unroll
    for (int o = 16; o > 0; o >>= 1) s += __shfl_xor_sync(0xffffffffu, s, o);
    if (lane == 0) summ[b * HID + h] = s + bias[h];
}

// ---------------------------------------------------------------------------
extern "C" void kernel_launch(void* const* d_in, const int* in_sizes, int n_in,
                              void* d_out, int out_size)
{
    const float* trg  = (const float*)d_in[0];
    // d_in[1] = src (unused, n_layers == 0)
    const float* W    = (const float*)d_in[2];
    const float* bias = (const float*)d_in[3];

    float* out   = (float*)d_out;
    float* summ  = out;                   // [32, 1024]
    float* norm1 = out + BATCH * HID;     // [32, 2048]

    __half* trgh; cudaGetSymbolAddress((void**)&trgh, g_trgh);
    __half* wh;   cudaGetSymbolAddress((void**)&wh,   g_wh);

    cudaFuncSetAttribute(k_norm_h, cudaFuncAttributeMaxDynamicSharedMemorySize, SMEM_NORM);

    k_cvt8<<<(HID * KDIM) / (256 * 8), 256>>>(W, wh);
    k_cvt8<<<((size_t)MROWS * KDIM) / (256 * 8), 256>>>(trg, trgh);
    k_norm_h<<<dim3(8, MROWS / 128), 256, SMEM_NORM>>>(bias);
    k_softmax<<<BATCH, 256>>>(norm1);
    k_pool<<<dim3(3, 8, BATCH), 256>>>();
    k_out<<<dim3(HID / 8, BATCH), 256>>>(W, bias, summ);
}